// round 6
// baseline (speedup 1.0000x reference)
#include <cuda_runtime.h>
#include <cuda_fp16.h>
#include <cstdint>

// ---------------- problem constants ----------------
#define B_    8
#define K_    128
#define S_    256
#define NOUT  16384
#define M_    2048
#define BM    128
#define BN    64
#define BK    32
#define NKB   4
#define STAGE_BYTES (BM * 64 + BN * 64)        // 8KB A + 4KB B = 12KB
#define SM_TOTAL (4 * STAGE_BYTES)             // 48KB (>= 34.8KB epilogue buf)

// ---------------- scratch: fp16, K-major ----------------
__device__ __half g_A[M_ * K_];      // 512 KB
__device__ __half g_B[NOUT * K_];    //   4 MB

// ---------------- helpers ----------------
__device__ __forceinline__ uint32_t smem_u32(const void* p) {
    uint32_t a;
    asm("{ .reg .u64 t; cvta.to.shared.u64 t, %1; cvt.u32.u64 %0, t; }" : "=r"(a) : "l"(p));
    return a;
}
__device__ __forceinline__ void cp_async16(uint32_t saddr, const void* gaddr) {
    asm volatile("cp.async.cg.shared.global [%0], [%1], 16;" :: "r"(saddr), "l"(gaddr));
}
__device__ __forceinline__ void cp_commit() {
    asm volatile("cp.async.commit_group;" ::: "memory");
}
template <int N>
__device__ __forceinline__ void cp_wait() {
    asm volatile("cp.async.wait_group %0;" :: "n"(N) : "memory");
}
__device__ __forceinline__ void ldsm4(uint32_t& r0, uint32_t& r1, uint32_t& r2, uint32_t& r3,
                                      uint32_t addr) {
    asm volatile("ldmatrix.sync.aligned.m8n8.x4.shared.b16 {%0,%1,%2,%3}, [%4];"
                 : "=r"(r0), "=r"(r1), "=r"(r2), "=r"(r3) : "r"(addr));
}
__device__ __forceinline__ void mma16816(float* d, uint32_t a0, uint32_t a1, uint32_t a2,
                                         uint32_t a3, uint32_t b0, uint32_t b1) {
    asm volatile(
        "mma.sync.aligned.m16n8k16.row.col.f32.f16.f16.f32 "
        "{%0,%1,%2,%3}, {%4,%5,%6,%7}, {%8,%9}, {%0,%1,%2,%3};"
        : "+f"(d[0]), "+f"(d[1]), "+f"(d[2]), "+f"(d[3])
        : "r"(a0), "r"(a1), "r"(a2), "r"(a3), "r"(b0), "r"(b1));
}

#define SWZ(row, c) ((c) ^ (((row) >> 1) & 3))
#define ESTRIDE 68

// ---------------- fused pre-kernel ----------------
__global__ __launch_bounds__(256)
void convert_kernel(const float* __restrict__ y, const float* __restrict__ W) {
    __shared__ float tile[32][33];
    const int bid = blockIdx.x;
    const float* src;
    __half* dst;
    int NC, c_t, k_t;
    if (bid < 2048) {
        c_t = bid >> 2; k_t = bid & 3;
        src = W; dst = g_B; NC = NOUT;
    } else {
        int yb = bid - 2048;
        int z  = yb >> 5;
        c_t = (yb >> 2) & 7; k_t = yb & 3;
        src = y + (size_t)z * K_ * S_;
        dst = g_A + (size_t)z * S_ * K_;
        NC = S_;
    }
    const int tx = threadIdx.x & 31;
    const int ty = threadIdx.x >> 5;
    const int c0 = c_t * 32, k0 = k_t * 32;

    #pragma unroll
    for (int r = 0; r < 4; ++r)
        tile[ty + 8 * r][tx] = src[(size_t)(k0 + ty + 8 * r) * NC + c0 + tx];
    __syncthreads();
    #pragma unroll
    for (int r = 0; r < 4; ++r) {
        int cc = c0 + ty + 8 * r;
        dst[(size_t)cc * K_ + k0 + tx] = __float2half(tile[tx][ty + 8 * r]);
    }
}

// ---------------- main GEMM kernel ----------------
__global__ __launch_bounds__(256, 3)
void gemm_fp16_kernel(float* __restrict__ out) {
    extern __shared__ char smem[];
    const uint32_t sbase = smem_u32(smem);
    const int tid  = threadIdx.x;
    const int lane = tid & 31;
    const int w    = tid >> 5;
    const int wm   = w >> 1;      // 0..3  (32-row strip)
    const int wn   = w & 1;       // 0..1  (32-col strip)
    const int bx   = blockIdx.x;  // n tile 0..255
    const int by   = blockIdx.y;  // m tile 0..15

    const __half* gA = g_A + (size_t)by * BM * K_;
    const __half* gB = g_B + (size_t)bx * BN * K_;

    float acc[2][4][4];
    #pragma unroll
    for (int i = 0; i < 2; ++i)
        #pragma unroll
        for (int j = 0; j < 4; ++j)
            #pragma unroll
            for (int k = 0; k < 4; ++k)
                acc[i][j][k] = 0.0f;

    // ---- prefetch ALL four K-chunks (one stage each) ----
    #pragma unroll
    for (int kb = 0; kb < NKB; ++kb) {
        const int kk0 = kb * BK;
        const uint32_t st = sbase + kb * STAGE_BYTES;
        #pragma unroll
        for (int it = 0; it < 2; ++it) {       // A: 512 chunks
            int ch  = tid + it * 256;
            int row = ch >> 2, c = ch & 3;
            cp_async16(st + row * 64 + (SWZ(row, c) << 4),
                       gA + (size_t)row * K_ + kk0 + c * 8);
        }
        {                                       // B: 256 chunks
            int row = tid >> 2, c = tid & 3;
            cp_async16(st + BM * 64 + row * 64 + (SWZ(row, c) << 4),
                       gB + (size_t)row * K_ + kk0 + c * 8);
        }
        cp_commit();
    }

    auto compute = [&](int kb) {
        const uint32_t Ab = sbase + kb * STAGE_BYTES;
        const uint32_t Bb = Ab + BM * 64;
        #pragma unroll
        for (int k16 = 0; k16 < 2; ++k16) {
            uint32_t br[4][2];
            #pragma unroll
            for (int ng = 0; ng < 2; ++ng) {
                int rown = wn * 32 + ng * 16 + ((lane >> 4) << 3) + (lane & 7);
                int cg   = k16 * 2 + ((lane >> 3) & 1);
                uint32_t b0, b1, b2, b3;
                ldsm4(b0, b1, b2, b3, Bb + rown * 64 + (SWZ(rown, cg) << 4));
                br[ng * 2][0] = b0;     br[ng * 2][1] = b1;
                br[ng * 2 + 1][0] = b2; br[ng * 2 + 1][1] = b3;
            }
            #pragma unroll
            for (int mt = 0; mt < 2; ++mt) {
                int rowm = wm * 32 + mt * 16 + (lane & 15);
                int cg   = k16 * 2 + (lane >> 4);
                uint32_t a0, a1, a2, a3;
                ldsm4(a0, a1, a2, a3, Ab + rowm * 64 + (SWZ(rowm, cg) << 4));
                #pragma unroll
                for (int nt = 0; nt < 4; ++nt)
                    mma16816(acc[mt][nt], a0, a1, a2, a3, br[nt][0], br[nt][1]);
            }
        }
    };

    cp_wait<3>(); __syncthreads(); compute(0);
    cp_wait<2>(); __syncthreads(); compute(1);
    cp_wait<1>(); __syncthreads(); compute(2);
    cp_wait<0>(); __syncthreads(); compute(3);

    // ---- epilogue: single smem round, warp-coherent float4 stores ----
    __syncthreads();
    float* ebuf = (float*)smem;               // [128][ESTRIDE]
    #pragma unroll
    for (int mt = 0; mt < 2; ++mt) {
        int r0 = wm * 32 + mt * 16 + (lane >> 2);
        #pragma unroll
        for (int nt = 0; nt < 4; ++nt) {
            int col = wn * 32 + nt * 8 + ((lane & 3) << 1);
            *(float2*)&ebuf[r0 * ESTRIDE + col] =
                make_float2(acc[mt][nt][0], acc[mt][nt][1]);
            *(float2*)&ebuf[(r0 + 8) * ESTRIDE + col] =
                make_float2(acc[mt][nt][2], acc[mt][nt][3]);
        }
    }
    __syncthreads();

    const int nn = by >> 1;
    #pragma unroll
    for (int k = 0; k < 8; ++k) {
        int j4 = w + 8 * (k & 1);             // 0..15 local j-quad
        int r  = (k >> 1) * 32 + lane;        // 0..127 row
        int sg = (by & 1) * 128 + r;
        int yy = sg >> 4, zz = sg & 15;
        float4 v = *(float4*)&ebuf[r * ESTRIDE + j4 * 4];
        size_t addr = (size_t)nn * 4194304
                    + (size_t)(bx * 4 + (j4 >> 2)) * 4096
                    + yy * 256 + (j4 & 3) * 64 + zz * 4;
        *(float4*)(out + addr) = v;
    }
}

// ---------------- launch ----------------
extern "C" void kernel_launch(void* const* d_in, const int* in_sizes, int n_in,
                              void* d_out, int out_size) {
    const float* y = (const float*)d_in[0];   // [8][128][256]
    const float* W = (const float*)d_in[1];   // [128][16384]
    float* out = (float*)d_out;

    convert_kernel<<<2304, 256>>>(y, W);

    cudaFuncSetAttribute(gemm_fp16_kernel,
                         cudaFuncAttributeMaxDynamicSharedMemorySize, SM_TOTAL);
    dim3 grid(NOUT / BN, M_ / BM);   // (256, 16)
    gemm_fp16_kernel<<<grid, 256, SM_TOTAL>>>(out);
}

// round 7
// speedup vs baseline: 1.2892x; 1.2892x over previous
#include <cuda_runtime.h>
#include <cuda_fp16.h>
#include <cstdint>

// ---------------- problem constants ----------------
#define B_    8
#define K_    128
#define S_    256
#define NOUT  16384
#define M_    2048
#define BM    128
#define BN    128
#define BK    32
#define NKB   4
#define STAGE_BYTES (BM * 64 + BN * 64)        // 16KB per stage
#define SM_TOTAL (NKB * STAGE_BYTES)           // 64KB, full-K prefetch

// ---------------- scratch: fp16, K-major ----------------
__device__ __half g_A[M_ * K_];      // 512 KB
__device__ __half g_B[NOUT * K_];    //   4 MB

// ---------------- helpers ----------------
__device__ __forceinline__ uint32_t smem_u32(const void* p) {
    uint32_t a;
    asm("{ .reg .u64 t; cvta.to.shared.u64 t, %1; cvt.u32.u64 %0, t; }" : "=r"(a) : "l"(p));
    return a;
}
__device__ __forceinline__ void cp_async16(uint32_t saddr, const void* gaddr) {
    asm volatile("cp.async.cg.shared.global [%0], [%1], 16;" :: "r"(saddr), "l"(gaddr));
}
__device__ __forceinline__ void cp_commit() {
    asm volatile("cp.async.commit_group;" ::: "memory");
}
template <int N>
__device__ __forceinline__ void cp_wait() {
    asm volatile("cp.async.wait_group %0;" :: "n"(N) : "memory");
}
__device__ __forceinline__ void ldsm4(uint32_t& r0, uint32_t& r1, uint32_t& r2, uint32_t& r3,
                                      uint32_t addr) {
    asm volatile("ldmatrix.sync.aligned.m8n8.x4.shared.b16 {%0,%1,%2,%3}, [%4];"
                 : "=r"(r0), "=r"(r1), "=r"(r2), "=r"(r3) : "r"(addr));
}
__device__ __forceinline__ void mma16816(float* d, uint32_t a0, uint32_t a1, uint32_t a2,
                                         uint32_t a3, uint32_t b0, uint32_t b1) {
    asm volatile(
        "mma.sync.aligned.m16n8k16.row.col.f32.f16.f16.f32 "
        "{%0,%1,%2,%3}, {%4,%5,%6,%7}, {%8,%9}, {%0,%1,%2,%3};"
        : "+f"(d[0]), "+f"(d[1]), "+f"(d[2]), "+f"(d[3])
        : "r"(a0), "r"(a1), "r"(a2), "r"(a3), "r"(b0), "r"(b1));
}

#define SWZ(row, c) ((c) ^ (((row) >> 1) & 3))

// ---------------- pre-kernel: 576 fat blocks, 4 k-tiles each ----------------
__global__ __launch_bounds__(256)
void convert_kernel(const float* __restrict__ y, const float* __restrict__ W) {
    __shared__ float tile[32][33];
    const int bid = blockIdx.x;
    const float* src;
    __half* dst;
    int NC, c0;
    if (bid < 512) {
        src = W; dst = g_B; NC = NOUT; c0 = bid * 32;
    } else {
        int t = bid - 512;
        int z = t >> 3;
        c0 = (t & 7) * 32;
        src = y + (size_t)z * K_ * S_;
        dst = g_A + (size_t)z * S_ * K_;
        NC = S_;
    }
    const int tx = threadIdx.x & 31;
    const int ty = threadIdx.x >> 5;

    for (int kt = 0; kt < 4; ++kt) {
        const int k0 = kt * 32;
        #pragma unroll
        for (int r = 0; r < 4; ++r)
            tile[ty + 8 * r][tx] = src[(size_t)(k0 + ty + 8 * r) * NC + c0 + tx];
        __syncthreads();
        #pragma unroll
        for (int r = 0; r < 4; ++r) {
            int cc = c0 + ty + 8 * r;
            dst[(size_t)cc * K_ + k0 + tx] = __float2half(tile[tx][ty + 8 * r]);
        }
        __syncthreads();
    }
}

// ---------------- main GEMM kernel ----------------
__global__ __launch_bounds__(256, 2)
void gemm_fp16_kernel(float* __restrict__ out) {
    extern __shared__ char smem[];
    const uint32_t sbase = smem_u32(smem);
    const int tid  = threadIdx.x;
    const int lane = tid & 31;
    const int w    = tid >> 5;
    const int wm   = w >> 2;      // 0..1 (64-row strip)
    const int wn   = w & 3;       // 0..3 (32-col strip)
    const int bx   = blockIdx.x;  // n tile 0..127
    const int by   = blockIdx.y;  // m tile 0..15

    const __half* gA = g_A + (size_t)by * BM * K_;
    const __half* gB = g_B + (size_t)bx * BN * K_;

    float acc[4][4][4];
    #pragma unroll
    for (int i = 0; i < 4; ++i)
        #pragma unroll
        for (int j = 0; j < 4; ++j)
            #pragma unroll
            for (int k = 0; k < 4; ++k)
                acc[i][j][k] = 0.0f;

    // ---- prefetch ALL four K-chunks ----
    #pragma unroll
    for (int kb = 0; kb < NKB; ++kb) {
        const int kk0 = kb * BK;
        const uint32_t st = sbase + kb * STAGE_BYTES;
        #pragma unroll
        for (int it = 0; it < 2; ++it) {
            int ch  = tid + it * 256;
            int row = ch >> 2, c = ch & 3;
            uint32_t off = row * 64 + (SWZ(row, c) << 4);
            cp_async16(st + off, gA + (size_t)row * K_ + kk0 + c * 8);
            cp_async16(st + BM * 64 + off, gB + (size_t)row * K_ + kk0 + c * 8);
        }
        cp_commit();
    }

    auto compute = [&](int kb) {
        const uint32_t Ab = sbase + kb * STAGE_BYTES;
        const uint32_t Bb = Ab + BM * 64;
        #pragma unroll
        for (int k16 = 0; k16 < 2; ++k16) {
            uint32_t br[4][2];
            #pragma unroll
            for (int ng = 0; ng < 2; ++ng) {
                int rown = wn * 32 + ng * 16 + ((lane >> 4) << 3) + (lane & 7);
                int cg   = k16 * 2 + ((lane >> 3) & 1);
                uint32_t b0, b1, b2, b3;
                ldsm4(b0, b1, b2, b3, Bb + rown * 64 + (SWZ(rown, cg) << 4));
                br[ng * 2][0] = b0;     br[ng * 2][1] = b1;
                br[ng * 2 + 1][0] = b2; br[ng * 2 + 1][1] = b3;
            }
            #pragma unroll
            for (int mt = 0; mt < 4; ++mt) {
                int rowm = wm * 64 + mt * 16 + (lane & 15);
                int cg   = k16 * 2 + (lane >> 4);
                uint32_t a0, a1, a2, a3;
                ldsm4(a0, a1, a2, a3, Ab + rowm * 64 + (SWZ(rowm, cg) << 4));
                #pragma unroll
                for (int nt = 0; nt < 4; ++nt)
                    mma16816(acc[mt][nt], a0, a1, a2, a3, br[nt][0], br[nt][1]);
            }
        }
    };

    cp_wait<3>(); __syncthreads(); compute(0);
    cp_wait<2>(); __syncthreads(); compute(1);
    cp_wait<1>(); __syncthreads(); compute(2);
    cp_wait<0>(); __syncthreads(); compute(3);

    // ---- epilogue: direct register -> gmem, perfectly coalesced STG.64 ----
    const int nn = by >> 1;
    float* obase = out + (size_t)nn * 4194304;
    #pragma unroll
    for (int mt = 0; mt < 4; ++mt) {
        #pragma unroll
        for (int nt = 0; nt < 4; ++nt) {
            int col = wn * 32 + nt * 8 + ((lane & 3) << 1);   // local j, even
            int j   = bx * BN + col;
            int p   = j >> 4;
            int q   = (j >> 2) & 3;
            int r   = j & 3;
            int row0 = wm * 64 + mt * 16 + (lane >> 2);
            int sg0  = (by & 1) * 128 + row0;
            // half 0: rows row0
            {
                size_t addr = (size_t)p * 4096 + (sg0 >> 4) * 256 + q * 64
                            + (sg0 & 15) * 4 + r;
                *(float2*)(obase + addr) = make_float2(acc[mt][nt][0], acc[mt][nt][1]);
            }
            // half 1: rows row0 + 8
            {
                int sg1 = sg0 + 8;
                size_t addr = (size_t)p * 4096 + (sg1 >> 4) * 256 + q * 64
                            + (sg1 & 15) * 4 + r;
                *(float2*)(obase + addr) = make_float2(acc[mt][nt][2], acc[mt][nt][3]);
            }
        }
    }
}

// ---------------- launch ----------------
extern "C" void kernel_launch(void* const* d_in, const int* in_sizes, int n_in,
                              void* d_out, int out_size) {
    const float* y = (const float*)d_in[0];   // [8][128][256]
    const float* W = (const float*)d_in[1];   // [128][16384]
    float* out = (float*)d_out;

    convert_kernel<<<576, 256>>>(y, W);

    cudaFuncSetAttribute(gemm_fp16_kernel,
                         cudaFuncAttributeMaxDynamicSharedMemorySize, SM_TOTAL);
    dim3 grid(NOUT / BN, M_ / BM);   // (128, 16)
    gemm_fp16_kernel<<<grid, 256, SM_TOTAL>>>(out);
}